// round 2
// baseline (speedup 1.0000x reference)
#include <cuda_runtime.h>
#include <cuda_fp16.h>
#include <cstdint>
#include <cstddef>

// ---------------------------------------------------------------------------
// Problem constants
// ---------------------------------------------------------------------------
#define TOKENS 4096   // M
#define IN_F   4096   // K
#define OUT_F  11008  // N

// GEMM tiling
#define BM 128
#define BN 128
#define BK 32
#define KTILES (IN_F / BK)   // 128
#define STAGES 4

#define A_STAGE_BYTES (BM * BK * 2)          // 8192
#define B_STAGE_BYTES (BN * BK * 2)          // 8192
#define STAGE_BYTES   (A_STAGE_BYTES + B_STAGE_BYTES)   // 16384
#define SMEM_TOTAL    (STAGES * STAGE_BYTES)            // 65536

// ---------------------------------------------------------------------------
// Device scratch (static — no cudaMalloc anywhere)
// ---------------------------------------------------------------------------
__device__ __half  g_q[(size_t)OUT_F * IN_F];    // ternary weights, fp16 exact
__device__ __half  g_xh[(size_t)TOKENS * IN_F];  // fp16(x)
__device__ double  g_partial[1024];
__device__ float   g_alpha;

// ---------------------------------------------------------------------------
// PTX helpers (baseline compute_103 — NO tcgen05/TMA-arch features)
// ---------------------------------------------------------------------------
__device__ __forceinline__ uint32_t smem_u32(const void* p) {
    uint32_t a;
    asm("{ .reg .u64 t; cvta.to.shared.u64 t, %1; cvt.u32.u64 %0, t; }"
        : "=r"(a) : "l"(p));
    return a;
}

__device__ __forceinline__ void cp_async16(uint32_t s, const void* g) {
    asm volatile(
        "{ .reg .u64 gg; cvta.to.global.u64 gg, %1; "
        "cp.async.cg.shared.global [%0], [gg], 16; }"
        :: "r"(s), "l"(g));
}
#define CP_COMMIT() asm volatile("cp.async.commit_group;" ::: "memory")
#define CP_WAIT(N)  asm volatile("cp.async.wait_group %0;" :: "n"(N) : "memory")

__device__ __forceinline__ void ldsm_x4(uint32_t& r0, uint32_t& r1,
                                        uint32_t& r2, uint32_t& r3, uint32_t a) {
    asm volatile("ldmatrix.sync.aligned.m8n8.x4.shared.b16 {%0,%1,%2,%3}, [%4];"
                 : "=r"(r0), "=r"(r1), "=r"(r2), "=r"(r3) : "r"(a));
}

__device__ __forceinline__ void mma16816(float& c0, float& c1, float& c2, float& c3,
                                         uint32_t a0, uint32_t a1, uint32_t a2, uint32_t a3,
                                         uint32_t b0, uint32_t b1) {
    asm volatile(
        "mma.sync.aligned.m16n8k16.row.col.f32.f16.f16.f32 "
        "{%0,%1,%2,%3}, {%4,%5,%6,%7}, {%8,%9}, {%0,%1,%2,%3};"
        : "+f"(c0), "+f"(c1), "+f"(c2), "+f"(c3)
        : "r"(a0), "r"(a1), "r"(a2), "r"(a3), "r"(b0), "r"(b1));
}

// 16B-chunk swizzle for 64B rows: chunk col cc (0..3), row r.
// Conflict-free for ldmatrix phases AND cp.async writes.
__device__ __forceinline__ uint32_t swz(uint32_t row, uint32_t cc) {
    return row * 64u + ((cc ^ ((row >> 1) & 3u)) << 4);
}

// ---------------------------------------------------------------------------
// Kernel 1: deterministic |W| partial sums (fp64 accumulators)
// ---------------------------------------------------------------------------
__global__ void reduce_abs_kernel(const float* __restrict__ w) {
    __shared__ double sh[256];
    const size_t n4 = (size_t)OUT_F * IN_F / 4;
    const float4* w4 = (const float4*)w;
    double acc = 0.0;
    for (size_t i = (size_t)blockIdx.x * 256 + threadIdx.x; i < n4;
         i += (size_t)1024 * 256) {
        float4 v = w4[i];
        acc += (double)fabsf(v.x) + (double)fabsf(v.y) +
               (double)fabsf(v.z) + (double)fabsf(v.w);
    }
    int tid = threadIdx.x;
    sh[tid] = acc;
    __syncthreads();
    for (int s = 128; s > 0; s >>= 1) {
        if (tid < s) sh[tid] += sh[tid + s];
        __syncthreads();
    }
    if (tid == 0) g_partial[blockIdx.x] = sh[0];
}

__global__ void finalize_alpha_kernel() {
    __shared__ double sh[256];
    int tid = threadIdx.x;
    double a = g_partial[tid] + g_partial[tid + 256] +
               g_partial[tid + 512] + g_partial[tid + 768];
    sh[tid] = a;
    __syncthreads();
    for (int s = 128; s > 0; s >>= 1) {
        if (tid < s) sh[tid] += sh[tid + s];
        __syncthreads();
    }
    if (tid == 0) g_alpha = (float)(sh[0] / ((double)OUT_F * (double)IN_F));
}

// ---------------------------------------------------------------------------
// Kernel 3: ternary quantize W -> fp16 {-1, 0, +1}
// ---------------------------------------------------------------------------
__global__ void quantize_kernel(const float* __restrict__ w) {
    const float a = g_alpha;
    size_t i = (size_t)blockIdx.x * blockDim.x + threadIdx.x;
    const size_t n4 = (size_t)OUT_F * IN_F / 4;
    if (i >= n4) return;
    float4 v = ((const float4*)w)[i];
    float q0 = (v.x > a) ? 1.0f : ((v.x < -a) ? -1.0f : 0.0f);
    float q1 = (v.y > a) ? 1.0f : ((v.y < -a) ? -1.0f : 0.0f);
    float q2 = (v.z > a) ? 1.0f : ((v.z < -a) ? -1.0f : 0.0f);
    float q3 = (v.w > a) ? 1.0f : ((v.w < -a) ? -1.0f : 0.0f);
    __half2* o = (__half2*)g_q;
    o[i * 2 + 0] = __half2(__float2half_rn(q0), __float2half_rn(q1));
    o[i * 2 + 1] = __half2(__float2half_rn(q2), __float2half_rn(q3));
}

// ---------------------------------------------------------------------------
// Kernel 4: x -> fp16
// ---------------------------------------------------------------------------
__global__ void convert_x_kernel(const float* __restrict__ x) {
    size_t i = (size_t)blockIdx.x * blockDim.x + threadIdx.x;
    const size_t n4 = (size_t)TOKENS * IN_F / 4;
    if (i >= n4) return;
    float4 v = ((const float4*)x)[i];
    __half2* o = (__half2*)g_xh;
    o[i * 2 + 0] = __half2(__float2half_rn(v.x), __float2half_rn(v.y));
    o[i * 2 + 1] = __half2(__float2half_rn(v.z), __float2half_rn(v.w));
}

// ---------------------------------------------------------------------------
// Kernel 5: fp16 HMMA GEMM, 4-stage cp.async pipeline
// out[m, n] = (sum_k xh[m,k] * q[n,k]) * scale[n] + bias[n]
// ---------------------------------------------------------------------------
__device__ __forceinline__ void load_stage(uint32_t sbase, int k0,
                                           const __half* __restrict__ xrow,
                                           const __half* __restrict__ qrow,
                                           int tid) {
    // A: 128 rows x 32 halves = 512 16B chunks; B: same.
#pragma unroll
    for (int j = 0; j < 2; j++) {
        int id = tid + j * 256;
        uint32_t row = (uint32_t)(id >> 2);
        uint32_t cc = (uint32_t)(id & 3);
        cp_async16(sbase + swz(row, cc),
                   xrow + (size_t)row * IN_F + k0 + cc * 8);
        cp_async16(sbase + A_STAGE_BYTES + swz(row, cc),
                   qrow + (size_t)row * IN_F + k0 + cc * 8);
    }
}

__global__ void __launch_bounds__(256, 2)
gemm_kernel(float* __restrict__ out, const float* __restrict__ scale,
            const float* __restrict__ bias) {
    extern __shared__ char smem[];
    const uint32_t sb = smem_u32(smem);
    const int tid = threadIdx.x;
    const int lane = tid & 31;
    const int wid = tid >> 5;
    const int warp_m = (wid & 1) * 64;
    const int warp_n = (wid >> 1) * 32;

    const int m0 = blockIdx.x * BM;   // m fastest -> q n-tiles L2-shared
    const int n0 = blockIdx.y * BN;

    const __half* xrow = g_xh + (size_t)m0 * IN_F;
    const __half* qrow = g_q + (size_t)n0 * IN_F;

    // Precompute ldmatrix swizzled offsets (relative to stage base).
    // A frag (m16k16) addr: row = warp_m + mt*16 + (lane&15), cc = ks*2 + (lane>>4)
    // B frag (n16k16) addr: row = warp_n + ng*16 + ((lane>>4)<<3) + (lane&7),
    //                       cc = ks*2 + ((lane>>3)&1)
    uint32_t offA[4][2], offB[2][2];
#pragma unroll
    for (int mt = 0; mt < 4; mt++) {
        uint32_t row = (uint32_t)(warp_m + mt * 16 + (lane & 15));
        uint32_t c0 = (uint32_t)(lane >> 4);
#pragma unroll
        for (int ks = 0; ks < 2; ks++)
            offA[mt][ks] = swz(row, (uint32_t)(ks * 2) + c0);
    }
#pragma unroll
    for (int ng = 0; ng < 2; ng++) {
        uint32_t row = (uint32_t)(warp_n + ng * 16 + ((lane >> 4) << 3) + (lane & 7));
        uint32_t c0 = (uint32_t)((lane >> 3) & 1);
#pragma unroll
        for (int ks = 0; ks < 2; ks++)
            offB[ng][ks] = A_STAGE_BYTES + swz(row, (uint32_t)(ks * 2) + c0);
    }

    float acc[4][4][4];
#pragma unroll
    for (int mt = 0; mt < 4; mt++)
#pragma unroll
        for (int nt = 0; nt < 4; nt++)
#pragma unroll
            for (int j = 0; j < 4; j++) acc[mt][nt][j] = 0.0f;

    // Prologue: stages 0..2
#pragma unroll
    for (int s = 0; s < STAGES - 1; s++) {
        load_stage(sb + s * STAGE_BYTES, s * BK, xrow, qrow, tid);
        CP_COMMIT();
    }

    for (int kt = 0; kt < KTILES; kt++) {
        CP_WAIT(STAGES - 2);
        __syncthreads();

        int kn = kt + STAGES - 1;
        if (kn < KTILES)
            load_stage(sb + (kn & (STAGES - 1)) * STAGE_BYTES, kn * BK,
                       xrow, qrow, tid);
        CP_COMMIT();

        const uint32_t stage = sb + (kt & (STAGES - 1)) * STAGE_BYTES;
#pragma unroll
        for (int ks = 0; ks < 2; ks++) {
            uint32_t af[4][4];
            uint32_t bf[4][2];
#pragma unroll
            for (int mt = 0; mt < 4; mt++)
                ldsm_x4(af[mt][0], af[mt][1], af[mt][2], af[mt][3],
                        stage + offA[mt][ks]);
#pragma unroll
            for (int ng = 0; ng < 2; ng++) {
                uint32_t r0, r1, r2, r3;
                ldsm_x4(r0, r1, r2, r3, stage + offB[ng][ks]);
                bf[2 * ng + 0][0] = r0; bf[2 * ng + 0][1] = r1;
                bf[2 * ng + 1][0] = r2; bf[2 * ng + 1][1] = r3;
            }
#pragma unroll
            for (int mt = 0; mt < 4; mt++)
#pragma unroll
                for (int nt = 0; nt < 4; nt++)
                    mma16816(acc[mt][nt][0], acc[mt][nt][1],
                             acc[mt][nt][2], acc[mt][nt][3],
                             af[mt][0], af[mt][1], af[mt][2], af[mt][3],
                             bf[nt][0], bf[nt][1]);
        }
    }

    // Epilogue: scale + bias, direct fp32 stores.
#pragma unroll
    for (int nt = 0; nt < 4; nt++) {
        const int c = n0 + warp_n + nt * 8 + (lane & 3) * 2;
        const float s0 = __ldg(scale + c), s1 = __ldg(scale + c + 1);
        const float b0 = __ldg(bias + c), b1 = __ldg(bias + c + 1);
#pragma unroll
        for (int mt = 0; mt < 4; mt++) {
            const int r0 = m0 + warp_m + mt * 16 + (lane >> 2);
            float2 v0 = {acc[mt][nt][0] * s0 + b0, acc[mt][nt][1] * s1 + b1};
            float2 v1 = {acc[mt][nt][2] * s0 + b0, acc[mt][nt][3] * s1 + b1};
            *(float2*)(out + (size_t)r0 * OUT_F + c) = v0;
            *(float2*)(out + (size_t)(r0 + 8) * OUT_F + c) = v1;
        }
    }
}

// ---------------------------------------------------------------------------
// kernel_launch
// ---------------------------------------------------------------------------
extern "C" void kernel_launch(void* const* d_in, const int* in_sizes, int n_in,
                              void* d_out, int out_size) {
    const float* x      = (const float*)d_in[0];  // (4096, 4096)
    const float* weight = (const float*)d_in[1];  // (11008, 4096)
    const float* scale  = (const float*)d_in[2];  // (11008, 1)
    const float* bias   = (const float*)d_in[3];  // (11008,)
    float* out = (float*)d_out;                   // (4096, 11008)
    (void)in_sizes; (void)n_in; (void)out_size;

    reduce_abs_kernel<<<1024, 256>>>(weight);
    finalize_alpha_kernel<<<1, 256>>>();
    quantize_kernel<<<(int)(((size_t)OUT_F * IN_F / 4 + 255) / 256), 256>>>(weight);
    convert_x_kernel<<<(int)(((size_t)TOKENS * IN_F / 4 + 255) / 256), 256>>>(x);

    cudaFuncSetAttribute(gemm_kernel,
                         cudaFuncAttributeMaxDynamicSharedMemorySize, SMEM_TOTAL);
    dim3 grid(TOKENS / BM, OUT_F / BN);  // (32, 86)
    gemm_kernel<<<grid, 256, SMEM_TOTAL>>>(out, scale, bias);
}